// round 9
// baseline (speedup 1.0000x reference)
#include <cuda_runtime.h>
#include <cuda_bf16.h>

#define ND   16    // domains
#define NE   64    // embedding dim
#define NK   32    // bottleneck dim
#define CAP  8192  // per-domain token-list capacity (expected ~3277)

// ---- device scratch (allocation-free; zero-initialized at load) ----
__device__ int g_cnt[ND];
__device__ int g_done;             // last-block-out detector
__device__ int g_list[ND * CAP];   // position index t
__device__ int g_ltok[ND * CAP];   // token id x[t]

typedef unsigned long long ull;

__device__ __forceinline__ ull ffma2(ull a, ull b, ull c) {
    ull d;
    asm("fma.rn.f32x2 %0, %1, %2, %3;" : "=l"(d) : "l"(a), "l"(b), "l"(c));
    return d;
}
__device__ __forceinline__ float2 unpk(ull v) {
    unsigned lo, hi;
    asm("mov.b64 {%0, %1}, %2;" : "=r"(lo), "=r"(hi) : "l"(v));
    return make_float2(__uint_as_float(lo), __uint_as_float(hi));
}
__device__ __forceinline__ ull pk(float lo, float hi) {
    ull v;
    asm("mov.b64 %0, {%1, %2};" : "=l"(v) : "r"(__float_as_uint(lo)), "r"(__float_as_uint(hi)));
    return v;
}

// ------------------------------------------------------------------
// 1) fused: build per-domain token lists + coalesced base copy
// ------------------------------------------------------------------
__global__ __launch_bounds__(256)
void build_copy(const int* __restrict__ x,
                const unsigned char* __restrict__ membership,
                const float* __restrict__ table,
                float* __restrict__ out,
                int T) {
    __shared__ int scnt[ND];
    __shared__ int sbase[ND];
    __shared__ int stok[256];

    const int t = blockIdx.x * 256 + threadIdx.x;
    if (threadIdx.x < ND) scnt[threadIdx.x] = 0;
    __syncthreads();

    unsigned act = 0;
    int mypos[ND];
    int tok = 0;
    if (t < T) {
        tok = x[t];
        stok[threadIdx.x] = tok;
        const unsigned char* __restrict__ mrow = membership + (long)tok * ND;
        #pragma unroll
        for (int d = 0; d < ND; ++d) {
            if (mrow[d]) {
                act |= (1u << d);
                mypos[d] = atomicAdd(&scnt[d], 1);
            }
        }
    }
    __syncthreads();
    if (threadIdx.x < ND)
        sbase[threadIdx.x] = atomicAdd(&g_cnt[threadIdx.x], scnt[threadIdx.x]);
    __syncthreads();
    if (t < T) {
        #pragma unroll
        for (int d = 0; d < ND; ++d) {
            if (act & (1u << d)) {
                int pos = sbase[d] + mypos[d];
                if (pos < CAP) {
                    g_list[d * CAP + pos] = t;
                    g_ltok[d * CAP + pos] = tok;
                }
            }
        }
    }

    // coalesced base-embedding copy for this block's 256 tokens
    const float4* __restrict__ table4 = reinterpret_cast<const float4*>(table);
    float4* __restrict__ out4 = reinterpret_cast<float4*>(out);
    const long blk_base = (long)blockIdx.x * 256;
    for (int j = threadIdx.x; j < 256 * 16; j += 256) {
        const int tl = j >> 4;
        const int c  = j & 15;
        const long gt = blk_base + tl;
        if (gt < T)
            out4[gt * 16 + c] = __ldg(table4 + (long)stok[tl] * 16 + c);
    }
}

// ------------------------------------------------------------------
// 2) per-domain MLP: all weights in smem (W1 pre-packed f32x2),
//    packed f32x2 math, 4-token interleave, depth-2 prefetch,
//    self-cleaning counters (last block zeroes g_cnt).
// ------------------------------------------------------------------
#define BLK_PER_DOM 36
#define MLP_WARPS   4
#define W1U 34            // sw1p row stride in ull (16B-aligned rows, conflict-free LDS.128)
#define W2S 36            // sw2 row stride in floats (16B-aligned rows, conflict-free LDS.128)

__global__ __launch_bounds__(MLP_WARPS * 32, 4)
void domain_mlp(const float* __restrict__ W1,
                const float* __restrict__ W2,
                const float* __restrict__ table,
                float* __restrict__ out) {
    __shared__ ull   sw1p[NK * W1U];           // W1 packed: [k][j], j-th e-pair
    __shared__ float sw2[NE * W2S];            // W2 as [e][k] padded rows
    __shared__ float hs[4][MLP_WARPS][NE];
    __shared__ float us[4][MLP_WARPS][NK];

    const int w    = threadIdx.x >> 5;
    const int lane = threadIdx.x & 31;
    const int d     = blockIdx.x & 15;
    const int chunk = blockIdx.x >> 4;
    const int ws    = BLK_PER_DOM * MLP_WARPS;    // warps per domain (144)

    // ---- stage this domain's weights from NATIVE layout ----
    {
        const float* __restrict__ W1n = W1 + (d << 11);   // [e][k]
        const float* __restrict__ W2n = W2 + (d << 11);   // [k][e]
        // W1: pack (e=2j, e=2j+1) for lane k -> sw1p[k*W1U + j]
        for (int i = threadIdx.x; i < NK * NK; i += MLP_WARPS * 32) {
            int j = i >> 5, k = i & 31;     // j = e-pair index 0..31
            sw1p[k * W1U + j] = pk(W1n[(2 * j) * NK + k], W1n[(2 * j + 1) * NK + k]);
        }
        for (int i = threadIdx.x; i < NE * NK; i += MLP_WARPS * 32) {
            int k2 = i >> 6, e2 = i & 63;
            sw2[e2 * W2S + k2] = W2n[i];
        }
    }
    __syncthreads();

    int cnt = g_cnt[d];
    if (cnt > CAP) cnt = CAP;
    int i0 = chunk * MLP_WARPS + w;

    if (i0 < cnt) {
        const int* __restrict__ list = g_list + d * CAP;
        const int* __restrict__ ltok = g_ltok + d * CAP;

        const ulonglong2* __restrict__ w1r =
            reinterpret_cast<const ulonglong2*>(sw1p + lane * W1U);
        const ulonglong2* __restrict__ hp0 = reinterpret_cast<const ulonglong2*>(hs[0][w]);
        const ulonglong2* __restrict__ hp1 = reinterpret_cast<const ulonglong2*>(hs[1][w]);
        const ulonglong2* __restrict__ hp2 = reinterpret_cast<const ulonglong2*>(hs[2][w]);
        const ulonglong2* __restrict__ hp3 = reinterpret_cast<const ulonglong2*>(hs[3][w]);
        const ulonglong2* __restrict__ up0 = reinterpret_cast<const ulonglong2*>(us[0][w]);
        const ulonglong2* __restrict__ up1 = reinterpret_cast<const ulonglong2*>(us[1][w]);
        const ulonglong2* __restrict__ up2 = reinterpret_cast<const ulonglong2*>(us[2][w]);
        const ulonglong2* __restrict__ up3 = reinterpret_cast<const ulonglong2*>(us[3][w]);
        const ulonglong2* __restrict__ w2r0 = reinterpret_cast<const ulonglong2*>(sw2 + lane * W2S);
        const ulonglong2* __restrict__ w2r1 = reinterpret_cast<const ulonglong2*>(sw2 + (lane + 32) * W2S);
        const float2* __restrict__ table2 = reinterpret_cast<const float2*>(table);

        // ---- prefetch first group of 4 ----
        int  i1 = i0 + ws, i2 = i0 + 2 * ws, i3 = i0 + 3 * ws;
        bool v1 = (i1 < cnt), v2 = (i2 < cnt), v3 = (i3 < cnt);
        int t0 = __ldg(list + i0);
        int t1 = v1 ? __ldg(list + i1) : t0;
        int t2 = v2 ? __ldg(list + i2) : t0;
        int t3 = v3 ? __ldg(list + i3) : t0;
        int k0 = __ldg(ltok + i0);
        int k1 = v1 ? __ldg(ltok + i1) : k0;
        int k2_ = v2 ? __ldg(ltok + i2) : k0;
        int k3 = v3 ? __ldg(ltok + i3) : k0;
        float2 h0 = __ldg(table2 + (long)k0 * 32 + lane);
        float2 h1 = __ldg(table2 + (long)k1 * 32 + lane);
        float2 h2 = __ldg(table2 + (long)k2_ * 32 + lane);
        float2 h3 = __ldg(table2 + (long)k3 * 32 + lane);

        while (true) {
            __syncwarp();
            reinterpret_cast<float2*>(hs[0][w])[lane] = h0;
            reinterpret_cast<float2*>(hs[1][w])[lane] = h1;
            reinterpret_cast<float2*>(hs[2][w])[lane] = h2;
            reinterpret_cast<float2*>(hs[3][w])[lane] = h3;
            __syncwarp();

            const int  c0 = t0, c1 = t1, c2 = t2, c3 = t3;
            const bool cv1 = v1, cv2 = v2, cv3 = v3;

            // ---- prefetch next group (overlaps compute) ----
            i0 += 4 * ws; i1 += 4 * ws; i2 += 4 * ws; i3 += 4 * ws;
            const bool hasNext = (i0 < cnt);
            if (hasNext) {
                v1 = (i1 < cnt); v2 = (i2 < cnt); v3 = (i3 < cnt);
                t0 = __ldg(list + i0);
                t1 = v1 ? __ldg(list + i1) : t0;
                t2 = v2 ? __ldg(list + i2) : t0;
                t3 = v3 ? __ldg(list + i3) : t0;
                k0 = __ldg(ltok + i0);
                k1 = v1 ? __ldg(ltok + i1) : k0;
                k2_ = v2 ? __ldg(ltok + i2) : k0;
                k3 = v3 ? __ldg(ltok + i3) : k0;
                h0 = __ldg(table2 + (long)k0 * 32 + lane);
                h1 = __ldg(table2 + (long)k1 * 32 + lane);
                h2 = __ldg(table2 + (long)k2_ * 32 + lane);
                h3 = __ldg(table2 + (long)k3 * 32 + lane);
            }

            // ---- stage 1: u[k] = gelu(h · W1[:,k]); 8 independent chains ----
            ull a0x = 0, a0y = 0, a1x = 0, a1y = 0;
            ull a2x = 0, a2y = 0, a3x = 0, a3y = 0;
            #pragma unroll
            for (int i = 0; i < 16; ++i) {
                ulonglong2 wp = w1r[i];      // packed e-pairs (4i..4i+1),(4i+2..4i+3)
                ulonglong2 q0 = hp0[i], q1 = hp1[i], q2 = hp2[i], q3 = hp3[i];
                a0x = ffma2(wp.x, q0.x, a0x);  a0y = ffma2(wp.y, q0.y, a0y);
                a1x = ffma2(wp.x, q1.x, a1x);  a1y = ffma2(wp.y, q1.y, a1y);
                a2x = ffma2(wp.x, q2.x, a2x);  a2y = ffma2(wp.y, q2.y, a2y);
                a3x = ffma2(wp.x, q3.x, a3x);  a3y = ffma2(wp.y, q3.y, a3y);
            }
            float2 f0x = unpk(a0x), f0y = unpk(a0y);
            float2 f1x = unpk(a1x), f1y = unpk(a1y);
            float2 f2x = unpk(a2x), f2y = unpk(a2y);
            float2 f3x = unpk(a3x), f3y = unpk(a3y);
            const float s0 = (f0x.x + f0x.y) + (f0y.x + f0y.y);
            const float s1 = (f1x.x + f1x.y) + (f1y.x + f1y.y);
            const float s2 = (f2x.x + f2x.y) + (f2y.x + f2y.y);
            const float s3 = (f3x.x + f3x.y) + (f3y.x + f3y.y);
            const float RS2 = 0.70710678118654752f;
            us[0][w][lane] = 0.5f * s0 * (1.f + erff(s0 * RS2));
            us[1][w][lane] = 0.5f * s1 * (1.f + erff(s1 * RS2));
            us[2][w][lane] = 0.5f * s2 * (1.f + erff(s2 * RS2));
            us[3][w][lane] = 0.5f * s3 * (1.f + erff(s3 * RS2));
            __syncwarp();

            // ---- stage 2: corr[e] = u · W2[e][:]; 8 packed chains ----
            ull cA0 = 0, cA1 = 0, cB0 = 0, cB1 = 0;
            ull cC0 = 0, cC1 = 0, cD0 = 0, cD1 = 0;
            #pragma unroll
            for (int i = 0; i < 8; ++i) {
                ulonglong2 wa = w2r0[i];
                ulonglong2 wb = w2r1[i];
                ulonglong2 u0 = up0[i], u1 = up1[i], u2 = up2[i], u3 = up3[i];
                cA0 = ffma2(wa.x, u0.x, cA0); cA0 = ffma2(wa.y, u0.y, cA0);
                cA1 = ffma2(wb.x, u0.x, cA1); cA1 = ffma2(wb.y, u0.y, cA1);
                cB0 = ffma2(wa.x, u1.x, cB0); cB0 = ffma2(wa.y, u1.y, cB0);
                cB1 = ffma2(wb.x, u1.x, cB1); cB1 = ffma2(wb.y, u1.y, cB1);
                cC0 = ffma2(wa.x, u2.x, cC0); cC0 = ffma2(wa.y, u2.y, cC0);
                cC1 = ffma2(wb.x, u2.x, cC1); cC1 = ffma2(wb.y, u2.y, cC1);
                cD0 = ffma2(wa.x, u3.x, cD0); cD0 = ffma2(wa.y, u3.y, cD0);
                cD1 = ffma2(wb.x, u3.x, cD1); cD1 = ffma2(wb.y, u3.y, cD1);
            }
            float2 gA0 = unpk(cA0), gA1 = unpk(cA1);
            float2 gB0 = unpk(cB0), gB1 = unpk(cB1);
            float2 gC0 = unpk(cC0), gC1 = unpk(cC1);
            float2 gD0 = unpk(cD0), gD1 = unpk(cD1);

            atomicAdd(out + (long)c0 * NE + lane,      0.1f * (gA0.x + gA0.y));
            atomicAdd(out + (long)c0 * NE + lane + 32, 0.1f * (gA1.x + gA1.y));
            if (cv1) {
                atomicAdd(out + (long)c1 * NE + lane,      0.1f * (gB0.x + gB0.y));
                atomicAdd(out + (long)c1 * NE + lane + 32, 0.1f * (gB1.x + gB1.y));
            }
            if (cv2) {
                atomicAdd(out + (long)c2 * NE + lane,      0.1f * (gC0.x + gC0.y));
                atomicAdd(out + (long)c2 * NE + lane + 32, 0.1f * (gC1.x + gC1.y));
            }
            if (cv3) {
                atomicAdd(out + (long)c3 * NE + lane,      0.1f * (gD0.x + gD0.y));
                atomicAdd(out + (long)c3 * NE + lane + 32, 0.1f * (gD1.x + gD1.y));
            }

            if (!hasNext) break;
        }
    }

    // ---- common epilogue: last block out zeroes the counters ----
    __syncthreads();
    if (threadIdx.x == 0) {
        const int old = atomicAdd(&g_done, 1);
        if (old == (int)gridDim.x - 1) {
            #pragma unroll
            for (int i = 0; i < ND; ++i) g_cnt[i] = 0;
            __threadfence();
            g_done = 0;
        }
    }
}

extern "C" void kernel_launch(void* const* d_in, const int* in_sizes, int n_in,
                              void* d_out, int out_size) {
    const int*           x     = (const int*)d_in[0];
    const float*         table = (const float*)d_in[1];
    const float*         W1    = (const float*)d_in[2];
    const float*         W2    = (const float*)d_in[3];
    const unsigned char* mem   = (const unsigned char*)d_in[4];
    float* out = (float*)d_out;

    const int T = in_sizes[0];

    build_copy<<<(T + 255) / 256, 256>>>(x, mem, table, out, T);
    domain_mlp<<<ND * BLK_PER_DOM, MLP_WARPS * 32>>>(W1, W2, table, out);
}